// round 7
// baseline (speedup 1.0000x reference)
#include <cuda_runtime.h>
#include <cstdint>

// ---------------------------------------------------------------------------
// SESConv_H_H — TF32 mma.sync implicit conv.
// R6: input-row-major inner loop: B fragments for row u feed both
// (r=0,ky=u) and (r=1,ky=u-1)  =>  40% fewer B-fragment LDS.
// ---------------------------------------------------------------------------

#define SG    12
#define CIN   16
#define COUT  16
#define BATCH 8
#define HWD   128

#define TILE_W 32
#define TILE_H 16
#define PLANE_STRIDE 728        // 20*36=720 padded (pad never read)
#define XS_UINTS (CIN * PLANE_STRIDE)      // 11648
#define KS_UINTS 6400                      // 25 taps * 2 chunks * 128
#define SMEM_BYTES ((XS_UINTS + KS_UINTS) * 4)   // 72192 B

// Keff (tf32 bits): [g][ij][tap*2+ch][o*8 + q*2 + s], c = ch*8 + q + 4*s
__device__ uint32_t g_keff[SG * 4 * 50 * 128];

__device__ __forceinline__ uint32_t tf32r(float v) {
    uint32_t r;
    asm("cvt.rna.tf32.f32 %0, %1;" : "=r"(r) : "f"(v));
    return r;
}

__device__ __forceinline__ void mma_tf32(float* d,
                                         uint32_t a0, uint32_t a1,
                                         uint32_t a2, uint32_t a3,
                                         uint32_t b0, uint32_t b1) {
    asm volatile(
        "mma.sync.aligned.m16n8k8.row.col.f32.tf32.tf32.f32 "
        "{%0,%1,%2,%3}, {%4,%5,%6,%7}, {%8,%9}, {%0,%1,%2,%3};"
        : "+f"(d[0]), "+f"(d[1]), "+f"(d[2]), "+f"(d[3])
        : "r"(a0), "r"(a1), "r"(a2), "r"(a3), "r"(b0), "r"(b1));
}

__global__ void build_keff_kernel(const float* __restrict__ weight,
                                  const float* __restrict__ basis) {
    const int total = SG * 4 * 50 * 128;
    int idx = blockIdx.x * blockDim.x + threadIdx.x;
    if (idx >= total) return;
    const int within = idx % 6400;
    const int gij    = idx / 6400;
    const int g  = gij / 4;
    const int ij = gij % 4;
    const int blk = within / 128;     // tap*2 + ch
    const int r   = within % 128;
    const int tap = blk >> 1;
    const int ch  = blk & 1;
    const int o   = r >> 3;
    const int q   = (r >> 1) & 3;
    const int s   = r & 1;
    const int c   = ch * 8 + q + 4 * s;
    float v = 0.f;
#pragma unroll
    for (int f = 0; f < 9; ++f)
        v += weight[((o * CIN + c) * 4 + ij) * 9 + f] *
             basis[(f * SG + g) * 25 + tap];
    g_keff[idx] = tf32r(v);
}

__global__ void __launch_bounds__(256, 2)
ses_mma_kernel(const float* __restrict__ x, float* __restrict__ out) {
    extern __shared__ uint32_t dyn[];
    uint32_t* xs = dyn;                 // 16 planes, 20x36 halo, stride 728
    uint32_t* ks = dyn + XS_UINTS;      // Keff stage

    const int tid  = threadIdx.x;
    const int w    = tid >> 5;          // warp -> output rows 2w, 2w+1
    const int lane = tid & 31;
    const int grp  = lane >> 2;
    const int tig  = lane & 3;

    const int bz = blockIdx.z;
    const int b  = bz / SG;
    const int g  = bz % SG;
    const int nr = g / 3;
    const int ns = g % 3;
    const int tx0 = blockIdx.x * TILE_W;
    const int ty0 = blockIdx.y * TILE_H;

    int ijv[4];
    int nv = 0;
#pragma unroll
    for (int ij = 0; ij < 4; ++ij)
        if (ns + (ij & 1) < 3) ijv[nv++] = ij;

    float acc[2][4][4];
#pragma unroll
    for (int r = 0; r < 2; ++r)
#pragma unroll
        for (int cr = 0; cr < 4; ++cr)
#pragma unroll
            for (int q = 0; q < 4; ++q) acc[r][cr][q] = 0.f;

    for (int sIdx = 0; sIdx < nv; ++sIdx) {
        const int ij = ijv[sIdx];
        const int sp = ((nr + (ij >> 1)) & 3) * 3 + (ns + (ij & 1));

        // fill x tile (tf32-converted)
        for (int e = tid; e < CIN * 720; e += 256) {
            const int p   = e / 720;
            const int rem = e - p * 720;
            const int rr  = rem / 36;
            const int cc  = rem - rr * 36;
            const int gy = ty0 + rr - 2;
            const int gx = tx0 + cc - 2;
            float v = 0.f;
            if ((unsigned)gy < (unsigned)HWD && (unsigned)gx < (unsigned)HWD)
                v = __ldg(x + ((((size_t)b * CIN + p) * SG + sp) << 14) +
                          gy * HWD + gx);
            xs[p * PLANE_STRIDE + rr * 36 + cc] = tf32r(v);
        }
        // fill Keff stage
        const uint32_t* kp = g_keff + (size_t)(g * 4 + ij) * 6400;
        for (int e = tid; e < 6400; e += 256) ks[e] = kp[e];
        __syncthreads();

#pragma unroll
        for (int ch = 0; ch < 2; ++ch) {
            const uint32_t* xbase =
                xs + (ch * 8 + tig) * PLANE_STRIDE + 2 * w * 36 + grp;
            const uint32_t* kbase = ks + ch * 128 + grp * 8 + tig * 2;

#pragma unroll
            for (int kx = 0; kx < 5; ++kx) {
                // hold all 5 ky A-fragments in registers
                uint2 A0[5], A1[5];
#pragma unroll
                for (int ky = 0; ky < 5; ++ky) {
                    const uint32_t* ka = kbase + (ky * 5 + kx) * 256;
                    A0[ky] = *reinterpret_cast<const uint2*>(ka);
                    A1[ky] = *reinterpret_cast<const uint2*>(ka + 64);
                }
                // sweep 6 input rows; each feeds up to 2 (r,ky) pairs
#pragma unroll
                for (int u = 0; u < 6; ++u) {
                    const uint32_t* pr = xbase + u * 36 + kx;
                    uint32_t b0[4], b1[4];
#pragma unroll
                    for (int cr = 0; cr < 4; ++cr) {
                        b0[cr] = pr[cr * 8];
                        b1[cr] = pr[cr * 8 + 4 * PLANE_STRIDE];
                    }
                    if (u <= 4) {
#pragma unroll
                        for (int cr = 0; cr < 4; ++cr)
                            mma_tf32(acc[0][cr], A0[u].x, A1[u].x,
                                     A0[u].y, A1[u].y, b0[cr], b1[cr]);
                    }
                    if (u >= 1) {
#pragma unroll
                        for (int cr = 0; cr < 4; ++cr)
                            mma_tf32(acc[1][cr], A0[u - 1].x, A1[u - 1].x,
                                     A0[u - 1].y, A1[u - 1].y, b0[cr], b1[cr]);
                    }
                }
            }
        }
        __syncthreads();
    }

#pragma unroll
    for (int r = 0; r < 2; ++r) {
        const int row = ty0 + 2 * w + r;
#pragma unroll
        for (int cr = 0; cr < 4; ++cr) {
            const int px = tx0 + cr * 8 + tig * 2;
            float* o0 = out + ((((size_t)b * COUT + grp)     * SG + g) << 14) +
                        row * HWD + px;
            float* o1 = out + ((((size_t)b * COUT + grp + 8) * SG + g) << 14) +
                        row * HWD + px;
            *reinterpret_cast<float2*>(o0) =
                make_float2(acc[r][cr][0], acc[r][cr][1]);
            *reinterpret_cast<float2*>(o1) =
                make_float2(acc[r][cr][2], acc[r][cr][3]);
        }
    }
}

extern "C" void kernel_launch(void* const* d_in, const int* in_sizes, int n_in,
                              void* d_out, int out_size) {
    const float* x      = (const float*)d_in[0];
    const float* weight = (const float*)d_in[1];
    const float* basis  = (const float*)d_in[2];
    float* out = (float*)d_out;

    const int total = SG * 4 * 50 * 128;
    build_keff_kernel<<<(total + 255) / 256, 256>>>(weight, basis);

    cudaFuncSetAttribute(ses_mma_kernel,
                         cudaFuncAttributeMaxDynamicSharedMemorySize,
                         SMEM_BYTES);
    dim3 grid(HWD / TILE_W, HWD / TILE_H, BATCH * SG);
    ses_mma_kernel<<<grid, 256, SMEM_BYTES>>>(x, out);
}

// round 8
// speedup vs baseline: 1.0819x; 1.0819x over previous
#include <cuda_runtime.h>
#include <cstdint>

// ---------------------------------------------------------------------------
// SESConv_H_H — TF32 mma.sync implicit conv.
// R7: vectorized fragments. Pair-plane x layout -> B = LDS.64;
// thread-major Keff layout -> A = LDS.128. Same math as R5/R6.
// ---------------------------------------------------------------------------

#define SG    12
#define CIN   16
#define COUT  16
#define BATCH 8
#define HWD   128

#define TILE_W 32
#define TILE_H 16
#define PPS    1448             // pair-plane stride (2*720=1440, +8 banks skew)
#define XS_UINTS (8 * PPS)      // 11584
#define KS_UINTS 6400           // 25 taps * 2 chunks * 128
#define SMEM_BYTES ((XS_UINTS + KS_UINTS) * 4)   // 71936 B

// Keff (tf32 bits): [g][ij][(tap*2+ch)*128 + lane*4 + j]
// j -> (o = grp + 8*(j&1), c = ch*8 + tig + 4*(j>>1)), lane = grp*4+tig
__device__ uint32_t g_keff[SG * 4 * 50 * 128];

__device__ __forceinline__ uint32_t tf32r(float v) {
    uint32_t r;
    asm("cvt.rna.tf32.f32 %0, %1;" : "=r"(r) : "f"(v));
    return r;
}

__device__ __forceinline__ void mma_tf32(float* d, uint4 A, uint2 B) {
    asm volatile(
        "mma.sync.aligned.m16n8k8.row.col.f32.tf32.tf32.f32 "
        "{%0,%1,%2,%3}, {%4,%5,%6,%7}, {%8,%9}, {%0,%1,%2,%3};"
        : "+f"(d[0]), "+f"(d[1]), "+f"(d[2]), "+f"(d[3])
        : "r"(A.x), "r"(A.y), "r"(A.z), "r"(A.w), "r"(B.x), "r"(B.y));
}

__global__ void build_keff_kernel(const float* __restrict__ weight,
                                  const float* __restrict__ basis) {
    const int total = SG * 4 * 50 * 128;
    int idx = blockIdx.x * blockDim.x + threadIdx.x;
    if (idx >= total) return;
    const int within = idx % 6400;
    const int gij    = idx / 6400;
    const int g  = gij / 4;
    const int ij = gij % 4;
    const int blk = within / 128;     // tap*2 + ch
    const int r   = within % 128;
    const int tap = blk >> 1;
    const int ch  = blk & 1;
    const int lane = r >> 2;
    const int j    = r & 3;
    const int grp  = lane >> 2;
    const int tig  = lane & 3;
    const int o = grp + 8 * (j & 1);
    const int c = ch * 8 + tig + 4 * (j >> 1);
    float v = 0.f;
#pragma unroll
    for (int f = 0; f < 9; ++f)
        v += weight[((o * CIN + c) * 4 + ij) * 9 + f] *
             basis[(f * SG + g) * 25 + tap];
    g_keff[idx] = tf32r(v);
}

__global__ void __launch_bounds__(256, 2)
ses_mma_kernel(const float* __restrict__ x, float* __restrict__ out) {
    extern __shared__ uint32_t dyn[];
    uint32_t* xs = dyn;                 // 8 pair-planes, stride PPS
    uint32_t* ks = dyn + XS_UINTS;      // Keff stage

    const int tid  = threadIdx.x;
    const int w    = tid >> 5;          // warp -> output rows 2w, 2w+1
    const int lane = tid & 31;
    const int grp  = lane >> 2;
    const int tig  = lane & 3;

    const int bz = blockIdx.z;
    const int b  = bz / SG;
    const int g  = bz % SG;
    const int nr = g / 3;
    const int ns = g % 3;
    const int tx0 = blockIdx.x * TILE_W;
    const int ty0 = blockIdx.y * TILE_H;

    int ijv[4];
    int nv = 0;
#pragma unroll
    for (int ij = 0; ij < 4; ++ij)
        if (ns + (ij & 1) < 3) ijv[nv++] = ij;

    float acc[2][4][4];
#pragma unroll
    for (int r = 0; r < 2; ++r)
#pragma unroll
        for (int cr = 0; cr < 4; ++cr)
#pragma unroll
            for (int q = 0; q < 4; ++q) acc[r][cr][q] = 0.f;

    for (int sIdx = 0; sIdx < nv; ++sIdx) {
        const int ij = ijv[sIdx];
        const int sp = ((nr + (ij >> 1)) & 3) * 3 + (ns + (ij & 1));

        // fill x tile (pair-plane layout, tf32-converted)
        for (int e = tid; e < CIN * 720; e += 256) {
            const int p   = e / 720;
            const int rem = e - p * 720;
            const int rr  = rem / 36;
            const int cc  = rem - rr * 36;
            const int gy = ty0 + rr - 2;
            const int gx = tx0 + cc - 2;
            float v = 0.f;
            if ((unsigned)gy < (unsigned)HWD && (unsigned)gx < (unsigned)HWD)
                v = __ldg(x + ((((size_t)b * CIN + p) * SG + sp) << 14) +
                          gy * HWD + gx);
            const int chp = p >> 3;
            const int w8  = p & 7;
            const int pair = chp * 4 + (w8 & 3);
            const int h    = w8 >> 2;
            xs[pair * PPS + rem * 2 + h] = tf32r(v);
        }
        // fill Keff stage
        const uint32_t* kp = g_keff + (size_t)(g * 4 + ij) * 6400;
        for (int e = tid; e < 6400; e += 256) ks[e] = kp[e];
        __syncthreads();

#pragma unroll
        for (int ch = 0; ch < 2; ++ch) {
            const uint32_t* xbase =
                xs + (ch * 4 + tig) * PPS + (2 * w * 36 + grp) * 2;
            const uint32_t* kbase = ks + ch * 128 + lane * 4;

#pragma unroll
            for (int kx = 0; kx < 5; ++kx) {
                uint4 A[5];
#pragma unroll
                for (int ky = 0; ky < 5; ++ky)
                    A[ky] = *reinterpret_cast<const uint4*>(
                        kbase + (ky * 5 + kx) * 256);

                const uint32_t* pb = xbase + kx * 2;
#pragma unroll
                for (int u = 0; u < 6; ++u) {
                    uint2 Bv[4];
#pragma unroll
                    for (int cr = 0; cr < 4; ++cr)
                        Bv[cr] = *reinterpret_cast<const uint2*>(
                            pb + u * 72 + cr * 16);
                    if (u <= 4) {
#pragma unroll
                        for (int cr = 0; cr < 4; ++cr)
                            mma_tf32(acc[0][cr], A[u], Bv[cr]);
                    }
                    if (u >= 1) {
#pragma unroll
                        for (int cr = 0; cr < 4; ++cr)
                            mma_tf32(acc[1][cr], A[u - 1], Bv[cr]);
                    }
                }
            }
        }
        __syncthreads();
    }

#pragma unroll
    for (int r = 0; r < 2; ++r) {
        const int row = ty0 + 2 * w + r;
#pragma unroll
        for (int cr = 0; cr < 4; ++cr) {
            const int px = tx0 + cr * 8 + tig * 2;
            float* o0 = out + ((((size_t)b * COUT + grp)     * SG + g) << 14) +
                        row * HWD + px;
            float* o1 = out + ((((size_t)b * COUT + grp + 8) * SG + g) << 14) +
                        row * HWD + px;
            *reinterpret_cast<float2*>(o0) =
                make_float2(acc[r][cr][0], acc[r][cr][1]);
            *reinterpret_cast<float2*>(o1) =
                make_float2(acc[r][cr][2], acc[r][cr][3]);
        }
    }
}

extern "C" void kernel_launch(void* const* d_in, const int* in_sizes, int n_in,
                              void* d_out, int out_size) {
    const float* x      = (const float*)d_in[0];
    const float* weight = (const float*)d_in[1];
    const float* basis  = (const float*)d_in[2];
    float* out = (float*)d_out;

    const int total = SG * 4 * 50 * 128;
    build_keff_kernel<<<(total + 255) / 256, 256>>>(weight, basis);

    cudaFuncSetAttribute(ses_mma_kernel,
                         cudaFuncAttributeMaxDynamicSharedMemorySize,
                         SMEM_BYTES);
    dim3 grid(HWD / TILE_W, HWD / TILE_H, BATCH * SG);
    ses_mma_kernel<<<grid, 256, SMEM_BYTES>>>(x, out);
}

// round 9
// speedup vs baseline: 1.1629x; 1.0748x over previous
#include <cuda_runtime.h>
#include <cstdint>

// ---------------------------------------------------------------------------
// SESConv_H_H — TF32 mma.sync implicit conv.
// R8: chunk-major/pixel-major x layout (B loads = 256B contiguous per warp),
// 3 CTAs/SM via launch_bounds. Math identical to R5-R7.
// ---------------------------------------------------------------------------

#define SG    12
#define CIN   16
#define COUT  16
#define BATCH 8
#define HWD   128

#define TILE_W 32
#define TILE_H 16
#define NPIX   720               // 20 rows x 36 cols halo
#define SEC    5776              // NPIX*8 + 16 pad (uints per ch-section)
#define XS_UINTS (2 * SEC)       // 11552
#define KS_UINTS 6400            // 25 taps * 2 chunks * 128
#define SMEM_BYTES ((XS_UINTS + KS_UINTS) * 4)   // 71808 B

// Keff (tf32 bits): [g][ij][(tap*2+ch)*128 + lane*4 + j]
// j -> (o = grp + 8*(j&1), c = ch*8 + tig + 4*(j>>1)), lane = grp*4+tig
__device__ uint32_t g_keff[SG * 4 * 50 * 128];

__device__ __forceinline__ uint32_t tf32r(float v) {
    uint32_t r;
    asm("cvt.rna.tf32.f32 %0, %1;" : "=r"(r) : "f"(v));
    return r;
}

__device__ __forceinline__ void mma_tf32(float* d, uint4 A, uint2 B) {
    asm volatile(
        "mma.sync.aligned.m16n8k8.row.col.f32.tf32.tf32.f32 "
        "{%0,%1,%2,%3}, {%4,%5,%6,%7}, {%8,%9}, {%0,%1,%2,%3};"
        : "+f"(d[0]), "+f"(d[1]), "+f"(d[2]), "+f"(d[3])
        : "r"(A.x), "r"(A.y), "r"(A.z), "r"(A.w), "r"(B.x), "r"(B.y));
}

__global__ void build_keff_kernel(const float* __restrict__ weight,
                                  const float* __restrict__ basis) {
    const int total = SG * 4 * 50 * 128;
    int idx = blockIdx.x * blockDim.x + threadIdx.x;
    if (idx >= total) return;
    const int within = idx % 6400;
    const int gij    = idx / 6400;
    const int g  = gij / 4;
    const int ij = gij % 4;
    const int blk = within / 128;     // tap*2 + ch
    const int r   = within % 128;
    const int tap = blk >> 1;
    const int ch  = blk & 1;
    const int lane = r >> 2;
    const int j    = r & 3;
    const int grp  = lane >> 2;
    const int tig  = lane & 3;
    const int o = grp + 8 * (j & 1);
    const int c = ch * 8 + tig + 4 * (j >> 1);
    float v = 0.f;
#pragma unroll
    for (int f = 0; f < 9; ++f)
        v += weight[((o * CIN + c) * 4 + ij) * 9 + f] *
             basis[(f * SG + g) * 25 + tap];
    g_keff[idx] = tf32r(v);
}

__global__ void __launch_bounds__(256, 3)
ses_mma_kernel(const float* __restrict__ x, float* __restrict__ out) {
    extern __shared__ uint32_t dyn[];
    uint32_t* xs = dyn;                 // 2 ch-sections: [pix][tig*2+h]
    uint32_t* ks = dyn + XS_UINTS;      // Keff stage

    const int tid  = threadIdx.x;
    const int w    = tid >> 5;          // warp -> output rows 2w, 2w+1
    const int lane = tid & 31;
    const int grp  = lane >> 2;
    const int tig  = lane & 3;

    const int bz = blockIdx.z;
    const int b  = bz / SG;
    const int g  = bz % SG;
    const int nr = g / 3;
    const int ns = g % 3;
    const int tx0 = blockIdx.x * TILE_W;
    const int ty0 = blockIdx.y * TILE_H;

    int ijv[4];
    int nv = 0;
#pragma unroll
    for (int ij = 0; ij < 4; ++ij)
        if (ns + (ij & 1) < 3) ijv[nv++] = ij;

    float acc[2][4][4];
#pragma unroll
    for (int r = 0; r < 2; ++r)
#pragma unroll
        for (int cr = 0; cr < 4; ++cr)
#pragma unroll
            for (int q = 0; q < 4; ++q) acc[r][cr][q] = 0.f;

    for (int sIdx = 0; sIdx < nv; ++sIdx) {
        const int ij = ijv[sIdx];
        const int sp = ((nr + (ij >> 1)) & 3) * 3 + (ns + (ij & 1));

        // fill x tile: xs[ch*SEC + pix*8 + tig*2 + h], c = ch*8 + tig + 4*h
        for (int e = tid; e < CIN * NPIX; e += 256) {
            const int p   = e / NPIX;           // channel
            const int rem = e - p * NPIX;       // pixel
            const int rr  = rem / 36;
            const int cc  = rem - rr * 36;
            const int gy = ty0 + rr - 2;
            const int gx = tx0 + cc - 2;
            float v = 0.f;
            if ((unsigned)gy < (unsigned)HWD && (unsigned)gx < (unsigned)HWD)
                v = __ldg(x + ((((size_t)b * CIN + p) * SG + sp) << 14) +
                          gy * HWD + gx);
            const int ch = p >> 3;
            const int tg = p & 3;
            const int h  = (p >> 2) & 1;
            xs[ch * SEC + rem * 8 + tg * 2 + h] = tf32r(v);
        }
        // fill Keff stage
        const uint32_t* kp = g_keff + (size_t)(g * 4 + ij) * 6400;
        for (int e = tid; e < 6400; e += 256) ks[e] = kp[e];
        __syncthreads();

#pragma unroll
        for (int ch = 0; ch < 2; ++ch) {
            const uint32_t* kbase = ks + ch * 128 + lane * 4;
            const uint32_t* xsec =
                xs + ch * SEC + (2 * w * 36 + grp) * 8 + tig * 2;

#pragma unroll
            for (int kx = 0; kx < 5; ++kx) {
                uint4 A[5];
#pragma unroll
                for (int ky = 0; ky < 5; ++ky)
                    A[ky] = *reinterpret_cast<const uint4*>(
                        kbase + (ky * 5 + kx) * 256);

                const uint32_t* pb = xsec + kx * 8;
#pragma unroll
                for (int u = 0; u < 6; ++u) {
                    const uint32_t* pu = pb + u * 288;   // u * 36 pixels * 8
                    uint2 Bv[4];
#pragma unroll
                    for (int cr = 0; cr < 4; ++cr)
                        Bv[cr] = *reinterpret_cast<const uint2*>(pu + cr * 64);
                    if (u <= 4) {
#pragma unroll
                        for (int cr = 0; cr < 4; ++cr)
                            mma_tf32(acc[0][cr], A[u], Bv[cr]);
                    }
                    if (u >= 1) {
#pragma unroll
                        for (int cr = 0; cr < 4; ++cr)
                            mma_tf32(acc[1][cr], A[u - 1], Bv[cr]);
                    }
                }
            }
        }
        __syncthreads();
    }

#pragma unroll
    for (int r = 0; r < 2; ++r) {
        const int row = ty0 + 2 * w + r;
#pragma unroll
        for (int cr = 0; cr < 4; ++cr) {
            const int px = tx0 + cr * 8 + tig * 2;
            float* o0 = out + ((((size_t)b * COUT + grp)     * SG + g) << 14) +
                        row * HWD + px;
            float* o1 = out + ((((size_t)b * COUT + grp + 8) * SG + g) << 14) +
                        row * HWD + px;
            *reinterpret_cast<float2*>(o0) =
                make_float2(acc[r][cr][0], acc[r][cr][1]);
            *reinterpret_cast<float2*>(o1) =
                make_float2(acc[r][cr][2], acc[r][cr][3]);
        }
    }
}

extern "C" void kernel_launch(void* const* d_in, const int* in_sizes, int n_in,
                              void* d_out, int out_size) {
    const float* x      = (const float*)d_in[0];
    const float* weight = (const float*)d_in[1];
    const float* basis  = (const float*)d_in[2];
    float* out = (float*)d_out;

    const int total = SG * 4 * 50 * 128;
    build_keff_kernel<<<(total + 255) / 256, 256>>>(weight, basis);

    cudaFuncSetAttribute(ses_mma_kernel,
                         cudaFuncAttributeMaxDynamicSharedMemorySize,
                         SMEM_BYTES);
    dim3 grid(HWD / TILE_W, HWD / TILE_H, BATCH * SG);
    ses_mma_kernel<<<grid, 256, SMEM_BYTES>>>(x, out);
}

// round 10
// speedup vs baseline: 1.4477x; 1.2450x over previous
#include <cuda_runtime.h>
#include <cstdint>

// ---------------------------------------------------------------------------
// SESConv_H_H — TF32 mma.sync implicit conv.
// R9: fill loop stores uint2 channel-pairs (8-way STS conflict -> 2-way),
// Keff staged with uint4 copies. Compute loop identical to R8.
// ---------------------------------------------------------------------------

#define SG    12
#define CIN   16
#define COUT  16
#define BATCH 8
#define HWD   128

#define TILE_W 32
#define TILE_H 16
#define NPIX   720               // 20 rows x 36 cols halo
#define SEC    5776              // NPIX*8 + 16 pad (uints per ch-section)
#define XS_UINTS (2 * SEC)       // 11552
#define KS_UINTS 6400            // 25 taps * 2 chunks * 128
#define SMEM_BYTES ((XS_UINTS + KS_UINTS) * 4)   // 71808 B

// Keff (tf32 bits): [g][ij][(tap*2+ch)*128 + lane*4 + j]
// j -> (o = grp + 8*(j&1), c = ch*8 + tig + 4*(j>>1)), lane = grp*4+tig
__device__ uint32_t g_keff[SG * 4 * 50 * 128];

__device__ __forceinline__ uint32_t tf32r(float v) {
    uint32_t r;
    asm("cvt.rna.tf32.f32 %0, %1;" : "=r"(r) : "f"(v));
    return r;
}

__device__ __forceinline__ void mma_tf32(float* d, uint4 A, uint2 B) {
    asm volatile(
        "mma.sync.aligned.m16n8k8.row.col.f32.tf32.tf32.f32 "
        "{%0,%1,%2,%3}, {%4,%5,%6,%7}, {%8,%9}, {%0,%1,%2,%3};"
        : "+f"(d[0]), "+f"(d[1]), "+f"(d[2]), "+f"(d[3])
        : "r"(A.x), "r"(A.y), "r"(A.z), "r"(A.w), "r"(B.x), "r"(B.y));
}

__global__ void build_keff_kernel(const float* __restrict__ weight,
                                  const float* __restrict__ basis) {
    const int total = SG * 4 * 50 * 128;
    int idx = blockIdx.x * blockDim.x + threadIdx.x;
    if (idx >= total) return;
    const int within = idx % 6400;
    const int gij    = idx / 6400;
    const int g  = gij / 4;
    const int ij = gij % 4;
    const int blk = within / 128;     // tap*2 + ch
    const int r   = within % 128;
    const int tap = blk >> 1;
    const int ch  = blk & 1;
    const int lane = r >> 2;
    const int j    = r & 3;
    const int grp  = lane >> 2;
    const int tig  = lane & 3;
    const int o = grp + 8 * (j & 1);
    const int c = ch * 8 + tig + 4 * (j >> 1);
    float v = 0.f;
#pragma unroll
    for (int f = 0; f < 9; ++f)
        v += weight[((o * CIN + c) * 4 + ij) * 9 + f] *
             basis[(f * SG + g) * 25 + tap];
    g_keff[idx] = tf32r(v);
}

__global__ void __launch_bounds__(256, 3)
ses_mma_kernel(const float* __restrict__ x, float* __restrict__ out) {
    extern __shared__ uint32_t dyn[];
    uint32_t* xs = dyn;                 // 2 ch-sections: [pix][tig*2+h]
    uint32_t* ks = dyn + XS_UINTS;      // Keff stage

    const int tid  = threadIdx.x;
    const int w    = tid >> 5;          // warp -> output rows 2w, 2w+1
    const int lane = tid & 31;
    const int grp  = lane >> 2;
    const int tig  = lane & 3;

    const int bz = blockIdx.z;
    const int b  = bz / SG;
    const int g  = bz % SG;
    const int nr = g / 3;
    const int ns = g % 3;
    const int tx0 = blockIdx.x * TILE_W;
    const int ty0 = blockIdx.y * TILE_H;

    int ijv[4];
    int nv = 0;
#pragma unroll
    for (int ij = 0; ij < 4; ++ij)
        if (ns + (ij & 1) < 3) ijv[nv++] = ij;

    float acc[2][4][4];
#pragma unroll
    for (int r = 0; r < 2; ++r)
#pragma unroll
        for (int cr = 0; cr < 4; ++cr)
#pragma unroll
            for (int q = 0; q < 4; ++q) acc[r][cr][q] = 0.f;

    for (int sIdx = 0; sIdx < nv; ++sIdx) {
        const int ij = ijv[sIdx];
        const int sp = ((nr + (ij >> 1)) & 3) * 3 + (ns + (ij & 1));
        const float* xb =
            x + ((((size_t)b * CIN) * SG + sp) << 14);   // + c*(SG<<14)

        // fill: one uint2 (c, c+4) per element-pair. 5760 pairs.
        // e: tg = e&3, pix = (e>>2)%720, ch = (e>>2)/720
        for (int e = tid; e < 2 * 4 * NPIX; e += 256) {
            const int tg  = e & 3;
            const int pe  = e >> 2;
            const int ch  = pe / NPIX;
            const int pix = pe - ch * NPIX;
            const int rr  = pix / 36;
            const int cc  = pix - rr * 36;
            const int gy = ty0 + rr - 2;
            const int gx = tx0 + cc - 2;
            const int c0 = ch * 8 + tg;
            uint2 val = make_uint2(0u, 0u);
            if ((unsigned)gy < (unsigned)HWD && (unsigned)gx < (unsigned)HWD) {
                const size_t off = (size_t)gy * HWD + gx;
                const size_t pstride = (size_t)SG << 14;
                val.x = tf32r(__ldg(xb + (size_t)c0 * pstride + off));
                val.y = tf32r(__ldg(xb + (size_t)(c0 + 4) * pstride + off));
            }
            *reinterpret_cast<uint2*>(xs + ch * SEC + pix * 8 + tg * 2) = val;
        }
        // fill Keff stage (uint4 copies, conflict-free)
        const uint4* kp =
            reinterpret_cast<const uint4*>(g_keff + (size_t)(g * 4 + ij) * 6400);
        uint4* kd = reinterpret_cast<uint4*>(ks);
        for (int e = tid; e < KS_UINTS / 4; e += 256) kd[e] = kp[e];
        __syncthreads();

#pragma unroll
        for (int ch = 0; ch < 2; ++ch) {
            const uint32_t* kbase = ks + ch * 128 + lane * 4;
            const uint32_t* xsec =
                xs + ch * SEC + (2 * w * 36 + grp) * 8 + tig * 2;

#pragma unroll
            for (int kx = 0; kx < 5; ++kx) {
                uint4 A[5];
#pragma unroll
                for (int ky = 0; ky < 5; ++ky)
                    A[ky] = *reinterpret_cast<const uint4*>(
                        kbase + (ky * 5 + kx) * 256);

                const uint32_t* pb = xsec + kx * 8;
#pragma unroll
                for (int u = 0; u < 6; ++u) {
                    const uint32_t* pu = pb + u * 288;   // u * 36 pixels * 8
                    uint2 Bv[4];
#pragma unroll
                    for (int cr = 0; cr < 4; ++cr)
                        Bv[cr] = *reinterpret_cast<const uint2*>(pu + cr * 64);
                    if (u <= 4) {
#pragma unroll
                        for (int cr = 0; cr < 4; ++cr)
                            mma_tf32(acc[0][cr], A[u], Bv[cr]);
                    }
                    if (u >= 1) {
#pragma unroll
                        for (int cr = 0; cr < 4; ++cr)
                            mma_tf32(acc[1][cr], A[u - 1], Bv[cr]);
                    }
                }
            }
        }
        __syncthreads();
    }

#pragma unroll
    for (int r = 0; r < 2; ++r) {
        const int row = ty0 + 2 * w + r;
#pragma unroll
        for (int cr = 0; cr < 4; ++cr) {
            const int px = tx0 + cr * 8 + tig * 2;
            float* o0 = out + ((((size_t)b * COUT + grp)     * SG + g) << 14) +
                        row * HWD + px;
            float* o1 = out + ((((size_t)b * COUT + grp + 8) * SG + g) << 14) +
                        row * HWD + px;
            *reinterpret_cast<float2*>(o0) =
                make_float2(acc[r][cr][0], acc[r][cr][1]);
            *reinterpret_cast<float2*>(o1) =
                make_float2(acc[r][cr][2], acc[r][cr][3]);
        }
    }
}

extern "C" void kernel_launch(void* const* d_in, const int* in_sizes, int n_in,
                              void* d_out, int out_size) {
    const float* x      = (const float*)d_in[0];
    const float* weight = (const float*)d_in[1];
    const float* basis  = (const float*)d_in[2];
    float* out = (float*)d_out;

    const int total = SG * 4 * 50 * 128;
    build_keff_kernel<<<(total + 255) / 256, 256>>>(weight, basis);

    cudaFuncSetAttribute(ses_mma_kernel,
                         cudaFuncAttributeMaxDynamicSharedMemorySize,
                         SMEM_BYTES);
    dim3 grid(HWD / TILE_W, HWD / TILE_H, BATCH * SG);
    ses_mma_kernel<<<grid, 256, SMEM_BYTES>>>(x, out);
}